// round 15
// baseline (speedup 1.0000x reference)
#include <cuda_runtime.h>
#include <cuda_bf16.h>
#include <cstdint>

// ---------------------------------------------------------------------------
// Problem constants
// ---------------------------------------------------------------------------
constexpr int Bsz = 8;
constexpr int S   = 768;
constexpr int Hd  = 768;
constexpr int NH  = 12;
constexpr int NL  = 5;
constexpr int BS  = Bsz * S;
constexpr long long HH = (long long)Hd * Hd;

typedef __nv_bfloat16 bf16;

// ---------------------------------------------------------------------------
// Scratch (hi-only)
// ---------------------------------------------------------------------------
__device__ float g_o  [BS * Hd];

__device__ bf16 g_hs_h [BS * Hd];
__device__ bf16 g_q_h  [BS * Hd];
__device__ bf16 g_k_h  [BS * Hd];
__device__ bf16 g_Qh   [BS * Hd];
__device__ bf16 g_Kh   [BS * Hd];
__device__ bf16 g_Vh   [BS * Hd];
__device__ bf16 g_ctx_h[BS * Hd];
__device__ bf16 g_al_h [BS * Hd];

__device__ bf16 g_Wq_h [NL * Hd * Hd];
__device__ bf16 g_Wk_h [NL * Hd * Hd];
__device__ bf16 g_inw_h[3 * Hd * Hd];
__device__ bf16 g_ow_h [Hd * Hd];
__device__ bf16 g_pw_h [Hd * Hd];

__device__ bf16 g_F_h [NL * 8 * Hd * Hd];
__device__ bf16 g_FT_h[NL * 8 * Hd * Hd];
__device__ bf16 g_P1_h[NL * 4 * Hd * Hd];
__device__ bf16 g_QT1_h[NL * 4 * Hd * Hd];
__device__ bf16 g_P2_h[NL * 2 * Hd * Hd];
__device__ bf16 g_QT2_h[NL * 2 * Hd * Hd];
__device__ bf16 g_M_h [NL * Hd * Hd];
__device__ bf16 g_MT_h[NL * Hd * Hd];
__device__ bf16 g_GT_h[NL * Hd * Hd];

__device__ unsigned char g_fF [NL * 8];
__device__ unsigned char g_fP1[NL * 4];
__device__ unsigned char g_fP2[NL * 2];

// ---------------------------------------------------------------------------
// PTX helpers
// ---------------------------------------------------------------------------
__device__ __forceinline__ uint32_t smem_u32(const void* p) {
    return (uint32_t)__cvta_generic_to_shared(p);
}
__device__ __forceinline__ void cp16(uint32_t d, const void* s) {
    asm volatile("cp.async.cg.shared.global [%0], [%1], 16;"
                 :: "r"(d), "l"(s) : "memory");
}
__device__ __forceinline__ void cp_commit() {
    asm volatile("cp.async.commit_group;" ::: "memory");
}
template <int N>
__device__ __forceinline__ void cp_wait() {
    asm volatile("cp.async.wait_group %0;" :: "n"(N) : "memory");
}
__device__ __forceinline__ void ldsm4(uint32_t* r, uint32_t addr) {
    asm volatile("ldmatrix.sync.aligned.m8n8.x4.shared.b16 {%0,%1,%2,%3}, [%4];"
                 : "=r"(r[0]), "=r"(r[1]), "=r"(r[2]), "=r"(r[3]) : "r"(addr));
}
__device__ __forceinline__ void mma_bf16(float* d, const uint32_t* a,
                                         uint32_t b0, uint32_t b1) {
    asm volatile(
        "mma.sync.aligned.m16n8k16.row.col.f32.bf16.bf16.f32 "
        "{%0,%1,%2,%3}, {%4,%5,%6,%7}, {%8,%9}, {%0,%1,%2,%3};"
        : "+f"(d[0]), "+f"(d[1]), "+f"(d[2]), "+f"(d[3])
        : "r"(a[0]), "r"(a[1]), "r"(a[2]), "r"(a[3]), "r"(b0), "r"(b1));
}
__device__ __forceinline__ uint32_t pack_bf(bf16 a, bf16 b) {
    return (uint32_t)__bfloat16_as_ushort(a) |
           ((uint32_t)__bfloat16_as_ushort(b) << 16);
}
__device__ __forceinline__ uint32_t pack_f2(float a, float b) {
    return pack_bf(__float2bfloat16(a), __float2bfloat16(b));
}

// ---------------------------------------------------------------------------
// GEMM: 128x64 CTA tile, warp tile 32x32, BLK_K=32, 8 warps, 4-stage pipeline.
// Regs ~80 -> 3 CTAs/SM (24 warps, occ 37.5%) to fill the tensor pipe.
// ---------------------------------------------------------------------------
constexpr int TILE_A_B = 128 * 80;           // 10240 B (A: 128 rows x 80B)
constexpr int TILE_W_B = 64 * 80;            // 5120 B  (W: 64 rows x 80B)
constexpr int STAGE_B  = TILE_A_B + TILE_W_B;// 15360 B
constexpr int NSTAGE   = 4;
constexpr int GEMM_SMEM_FULL = NSTAGE * STAGE_B;  // 61440 B (> epilogue 34816)

__device__ __forceinline__ void gemm_issue(
    const bf16* __restrict__ Abase, const bf16* __restrict__ Wbase,
    int tid, uint32_t sstage, int kc)
{
#pragma unroll
    for (int i = 0; i < 3; i++) {
        const int task = i * 256 + tid;
        if (task < 512) {              // uniform per i (i<2 all-A, i==2 all-W)
            const int row = task >> 2, cs = task & 3;
            cp16(sstage + row * 80 + cs * 16,
                 Abase + (long long)row * Hd + kc * 32 + cs * 8);
        } else {
            const int t = task - 512;
            const int row = t >> 2, cs = t & 3;
            cp16(sstage + TILE_A_B + row * 80 + cs * 16,
                 Wbase + (long long)row * Hd + kc * 32 + cs * 8);
        }
    }
}

// MODE 0: fp32 out (+bias). MODE 1: bf16 out (+bias if non-null).
// MODE 2: bf16 out + transposed bf16 out (no bias).
template <int MODE>
__device__ void gemm_core(
    const bf16* __restrict__ A, const bf16* __restrict__ W,
    const float* __restrict__ bias,
    float* __restrict__ C, bf16* __restrict__ Ch, bf16* __restrict__ Th,
    int m0, int n0)
{
    extern __shared__ char dsm[];
    const int tid = threadIdx.x;
    const int wid = tid >> 5, lane = tid & 31;
    const int m_off = (wid & 3) * 32;          // 4 m-warps x 32 rows
    const int n_off = (wid >> 2) * 32;         // 2 n-warps x 32 cols
    const uint32_t sbase = smem_u32(dsm);

    const bf16* Ab = A + (long long)m0 * Hd;
    const bf16* Wb = W + (long long)n0 * Hd;

    // prologue: chunks 0..2 into stages 0..2
#pragma unroll
    for (int p = 0; p < NSTAGE - 1; p++) {
        gemm_issue(Ab, Wb, tid, sbase + p * STAGE_B, p);
        cp_commit();
    }

    float acc[2][4][4];
#pragma unroll
    for (int mi = 0; mi < 2; mi++)
#pragma unroll
        for (int j = 0; j < 4; j++)
#pragma unroll
            for (int e = 0; e < 4; e++) acc[mi][j][e] = 0.f;

    const int r_off = ((lane >> 3) & 1) * 8 + (lane & 7);
    const int c_off = (lane >> 4) * 8;

    for (int kc = 0; kc < 24; kc++) {
        cp_wait<NSTAGE - 2>();           // chunk kc ready
        __syncthreads();
        const uint32_t sb = sbase + (kc & (NSTAGE - 1)) * STAGE_B;
        const uint32_t aA = sb + (m_off + r_off) * 80 + c_off * 2;
        const uint32_t aW = sb + TILE_A_B + (n_off + r_off) * 80 + c_off * 2;

#pragma unroll
        for (int kk = 0; kk < 2; kk++) {
            uint32_t ah[2][4], bh[2][4];
#pragma unroll
            for (int t = 0; t < 2; t++)
                ldsm4(ah[t], aA + t * 16 * 80 + kk * 32);
#pragma unroll
            for (int u = 0; u < 2; u++)
                ldsm4(bh[u], aW + u * 16 * 80 + kk * 32);
#pragma unroll
            for (int u = 0; u < 2; u++)
#pragma unroll
                for (int mi = 0; mi < 2; mi++) {
                    mma_bf16(acc[mi][2 * u],     ah[mi], bh[u][0], bh[u][2]);
                    mma_bf16(acc[mi][2 * u + 1], ah[mi], bh[u][1], bh[u][3]);
                }
        }
        if (kc + NSTAGE - 1 < 24)
            gemm_issue(Ab, Wb, tid,
                       sbase + ((kc + NSTAGE - 1) & (NSTAGE - 1)) * STAGE_B,
                       kc + NSTAGE - 1);
        cp_commit();
    }
    __syncthreads();

    // stage accumulators through SMEM (f32 [128][68] = 34816 B <= 61440)
    float* sf = (float*)dsm;
    const int g = lane >> 2, t2 = (lane & 3) * 2;
#pragma unroll
    for (int mi = 0; mi < 2; mi++)
#pragma unroll
        for (int j = 0; j < 4; j++) {
            const int r = m_off + mi * 16 + g;
            const int c = n_off + j * 8 + t2;
            sf[r * 68 + c]           = acc[mi][j][0];
            sf[r * 68 + c + 1]       = acc[mi][j][1];
            sf[(r + 8) * 68 + c]     = acc[mi][j][2];
            sf[(r + 8) * 68 + c + 1] = acc[mi][j][3];
        }
    __syncthreads();

    if (MODE == 0) {
#pragma unroll 4
        for (int i = 0; i < 8; i++) {
            const int task = i * 256 + tid;
            const int row = task >> 4, c4 = (task & 15) * 4;
            float4 v = *(float4*)&sf[row * 68 + c4];
            v.x += bias[n0 + c4 + 0];
            v.y += bias[n0 + c4 + 1];
            v.z += bias[n0 + c4 + 2];
            v.w += bias[n0 + c4 + 3];
            *(float4*)(C + (long long)(m0 + row) * Hd + n0 + c4) = v;
        }
    } else {
#pragma unroll 4
        for (int i = 0; i < 8; i++) {
            const int task = i * 256 + tid;
            const int row = task >> 4, c4 = (task & 15) * 4;
            float4 v = *(float4*)&sf[row * 68 + c4];
            if (MODE == 1 && bias) {
                v.x += bias[n0 + c4 + 0];
                v.y += bias[n0 + c4 + 1];
                v.z += bias[n0 + c4 + 2];
                v.w += bias[n0 + c4 + 3];
            }
            *(uint2*)(Ch + (long long)(m0 + row) * Hd + n0 + c4) =
                make_uint2(pack_f2(v.x, v.y), pack_f2(v.z, v.w));
        }
        if (MODE == 2) {
            const int c = tid & 63;
            const int quarter = tid >> 6;
#pragma unroll 4
            for (int i = 0; i < 8; i++) {
                const int r4 = quarter * 32 + i * 4;
                float v0 = sf[(r4 + 0) * 68 + c];
                float v1 = sf[(r4 + 1) * 68 + c];
                float v2 = sf[(r4 + 2) * 68 + c];
                float v3 = sf[(r4 + 3) * 68 + c];
                *(uint2*)(Th + (long long)(n0 + c) * Hd + m0 + r4) =
                    make_uint2(pack_f2(v0, v1), pack_f2(v2, v3));
            }
        }
    }
}

// ---------------------------------------------------------------------------
// Chain product block (tile 128 x 64 now)
// ---------------------------------------------------------------------------
__device__ void chain_work(
    int zz,
    const bf16* __restrict__ sN_h, const bf16* __restrict__ sT_h,
    const unsigned char* __restrict__ fs,
    bf16* __restrict__ dN_h, bf16* __restrict__ dT_h,
    int spa, int dpa)
{
    const int a = zz / dpa, p = zz - a * dpa;
    const int li = a * spa + 2 * p;
    const unsigned char f1 = fs[li], f2 = fs[li + 1];
    const long long zo = (long long)zz * HH;
    const int m0 = blockIdx.y * 128, n0 = blockIdx.x * 64;
    const int tid = threadIdx.x;

    if (f1 & f2) {
#pragma unroll 4
        for (int i = 0; i < 8; i++) {
            const int task = i * 256 + tid;
            const int row = task >> 4, c4 = (task & 15) * 4;
            const int gr = m0 + row, gc = n0 + c4;
            float v0 = (gc + 0 == gr) ? 1.f : 0.f;
            float v1 = (gc + 1 == gr) ? 1.f : 0.f;
            float v2 = (gc + 2 == gr) ? 1.f : 0.f;
            float v3 = (gc + 3 == gr) ? 1.f : 0.f;
            const long long off = zo + (long long)gr * Hd + gc;
            uint2 hv = make_uint2(pack_f2(v0, v1), pack_f2(v2, v3));
            *(uint2*)(dN_h + off) = hv;
            *(uint2*)(dT_h + off) = hv;
        }
        return;
    }
    if (f1 | f2) {
        const long long so = (long long)(f1 ? li + 1 : li) * HH;
#pragma unroll 4
        for (int i = 0; i < 4; i++) {
            const int idx = i * 256 + tid;
            const int row = idx >> 3, c8 = (idx & 7) * 8;
            const long long doff = zo + (long long)(m0 + row) * Hd + n0 + c8;
            const long long soff = so + (long long)(m0 + row) * Hd + n0 + c8;
            *(uint4*)(dN_h + doff) = *(const uint4*)(sN_h + soff);
            *(uint4*)(dT_h + doff) = *(const uint4*)(sT_h + soff);
        }
        return;
    }
    gemm_core<2>(sN_h + (long long)li * HH, sT_h + (long long)(li + 1) * HH,
                 nullptr, nullptr, dN_h + zo, dT_h + zo, m0, n0);
}

// ---------------------------------------------------------------------------
// Merged launches (grid.x = 12 for N=768 in 64-col tiles)
// ---------------------------------------------------------------------------
__global__ __launch_bounds__(256, 3) void k_l1(
    const bf16* __restrict__ hs_h,
    const bf16* __restrict__ Wq_h, const bf16* __restrict__ Wk_h,
    const float* __restrict__ bq, const float* __restrict__ bk,
    const int* __restrict__ lang,
    bf16* __restrict__ q_h, bf16* __restrict__ k_h,
    const bf16* __restrict__ F_h, const bf16* __restrict__ FT_h,
    const unsigned char* __restrict__ fF,
    bf16* __restrict__ P1_h, bf16* __restrict__ QT1_h)
{
    const int z = blockIdx.z;
    if (z < 16) {
        const int fam = z >> 3, b = z & 7;
        const int lg = __ldg(&lang[b]);
        const long long ao = (long long)b * S * Hd;
        const bf16* wh = (fam ? Wk_h : Wq_h) + (long long)lg * HH;
        const float* bs = (fam ? bk : bq) + lg * Hd;
        bf16* oh = (fam ? k_h : q_h) + ao;
        gemm_core<1>(hs_h + ao, wh, bs, nullptr, oh, nullptr,
                     blockIdx.y * 128, blockIdx.x * 64);
    } else {
        chain_work(z - 16, F_h, FT_h, fF, P1_h, QT1_h, 8, 4);
    }
}

__global__ __launch_bounds__(256, 3) void k_l2(
    const bf16* __restrict__ q_h, const bf16* __restrict__ k_h,
    const bf16* __restrict__ hs_h,
    const bf16* __restrict__ inw_h, const float* __restrict__ in_b,
    bf16* __restrict__ Qh, bf16* __restrict__ Kh, bf16* __restrict__ Vh,
    const bf16* __restrict__ P1_h, const bf16* __restrict__ QT1_h,
    const unsigned char* __restrict__ fP1,
    bf16* __restrict__ P2_h, bf16* __restrict__ QT2_h)
{
    const int z = blockIdx.z;
    if (z < 24) {
        const int kind = z >> 3, b = z & 7;
        const long long ao = (long long)b * S * Hd;
        const bf16* ah;
        bf16* oh;
        if (kind == 0)      { ah = q_h;  oh = Qh; }
        else if (kind == 1) { ah = k_h;  oh = Kh; }
        else                { ah = hs_h; oh = Vh; }
        gemm_core<1>(ah + ao, inw_h + (long long)kind * HH, in_b + kind * Hd,
                     nullptr, oh + ao, nullptr,
                     blockIdx.y * 128, blockIdx.x * 64);
    } else {
        chain_work(z - 24, P1_h, QT1_h, fP1, P2_h, QT2_h, 4, 2);
    }
}

__global__ __launch_bounds__(256, 3) void k_l3(
    const bf16* __restrict__ ctx_h,
    const bf16* __restrict__ ow_h, const float* __restrict__ out_b,
    bf16* __restrict__ al_h,
    const bf16* __restrict__ P2_h, const bf16* __restrict__ QT2_h,
    const unsigned char* __restrict__ fP2,
    bf16* __restrict__ M_h, bf16* __restrict__ MT_h)
{
    const int z = blockIdx.z;
    if (z < 8) {
        const long long ao = (long long)z * S * Hd;
        gemm_core<1>(ctx_h + ao, ow_h, out_b, nullptr, al_h + ao, nullptr,
                     blockIdx.y * 128, blockIdx.x * 64);
    } else {
        chain_work(z - 8, P2_h, QT2_h, fP2, M_h, MT_h, 2, 1);
    }
}

// GT[l] = proj_w @ M[l]^T
__global__ __launch_bounds__(256, 3) void k_GT(
    const bf16* __restrict__ pw_h, const bf16* __restrict__ M_h,
    bf16* __restrict__ GT_h)
{
    const long long lo = (long long)blockIdx.z * HH;
    gemm_core<1>(pw_h, M_h + lo, nullptr, nullptr, GT_h + lo, nullptr,
                 blockIdx.y * 128, blockIdx.x * 64);
}

// final: out[b] = al[b] @ G[lang[b]] + proj_b
__global__ __launch_bounds__(256, 3) void k_final(
    const bf16* __restrict__ al_h, const bf16* __restrict__ GT_h,
    const float* __restrict__ proj_b, const int* __restrict__ lang,
    float* __restrict__ C)
{
    const int z = blockIdx.z;
    const int lg = __ldg(&lang[z]);
    const long long ao = (long long)z * S * Hd;
    gemm_core<0>(al_h + ao, GT_h + (long long)lg * HH, proj_b,
                 C + ao, nullptr, nullptr,
                 blockIdx.y * 128, blockIdx.x * 64);
}

// ---------------------------------------------------------------------------
// Tensor-core flash attention, hi-only (unchanged)
// ---------------------------------------------------------------------------
constexpr int AT_CHUNK = 64 * 80;
constexpr int AT_TILE  = 2 * AT_CHUNK;
constexpr int ATT_SMEM = 3 * AT_TILE;        // 30720 B

__global__ __launch_bounds__(256) void k_attn_tc(
    const bf16* __restrict__ Qg, const bf16* __restrict__ Kg,
    const bf16* __restrict__ Vg, bf16* __restrict__ Oh)
{
    extern __shared__ char dsm[];
    __shared__ float smax[4][2][16];
    __shared__ float larr[2][64];

    const int qt = blockIdx.x, h = blockIdx.y, b = blockIdx.z;
    const int tid = threadIdx.x;
    const int wid = tid >> 5, lane = tid & 31;
    const int wm = wid & 3, wn = wid >> 2;
    const int g = lane >> 2, t2 = (lane & 3) * 2;
    const int r_off = ((lane >> 3) & 1) * 8 + (lane & 7);
    const int c_off = (lane >> 4) * 8;

    const uint32_t sQ = smem_u32(dsm);
    const uint32_t sK = sQ + AT_TILE;
    const uint32_t sV = sQ + 2 * AT_TILE;
    unsigned short* vt16 = (unsigned short*)(dsm + 2 * AT_TILE);

    const long long qrow0 = (long long)(b * S + qt * 64);
    const int hoff = h * 64;

#pragma unroll
    for (int i = 0; i < 2; i++) {
        const int task = i * 256 + tid;
        const int row = task >> 3, rem = task & 7;
        const int chunk = rem >> 2, sub = rem & 3;
        cp16(sQ + chunk * AT_CHUNK + row * 80 + sub * 16,
             Qg + (qrow0 + row) * Hd + hoff + chunk * 32 + sub * 8);
    }
    cp_commit();

    float m0v = -1e30f, m1v = -1e30f, l0v = 0.f, l1v = 0.f;
    float ctx[8][4];
#pragma unroll
    for (int t = 0; t < 8; t++)
#pragma unroll
        for (int e = 0; e < 4; e++) ctx[t][e] = 0.f;

    for (int kt = 0; kt < 12; kt++) {
        __syncthreads();
        const long long krow0 = (long long)(b * S + kt * 64);
#pragma unroll
        for (int i = 0; i < 2; i++) {
            const int task = i * 256 + tid;
            const int row = task >> 3, rem = task & 7;
            const int chunk = rem >> 2, sub = rem & 3;
            cp16(sK + chunk * AT_CHUNK + row * 80 + sub * 16,
                 Kg + (krow0 + row) * Hd + hoff + chunk * 32 + sub * 8);
        }
        cp_commit();
#pragma unroll
        for (int i = 0; i < 8; i++) {
            const int task = i * 256 + tid;
            const int r = task >> 5;
            const int c2 = (task & 31) * 2;
            const uint32_t v2 = *(const uint32_t*)(Vg + (krow0 + r) * Hd + hoff + c2);
            const int base = (r >> 5) * 2560 + (r & 31);
            vt16[base + c2 * 40]       = (unsigned short)(v2 & 0xffff);
            vt16[base + (c2 + 1) * 40] = (unsigned short)(v2 >> 16);
        }
        cp_wait<0>();
        __syncthreads();

        float sacc[4][4];
#pragma unroll
        for (int t = 0; t < 4; t++)
#pragma unroll
            for (int e = 0; e < 4; e++) sacc[t][e] = 0.f;

#pragma unroll
        for (int c = 0; c < 2; c++) {
#pragma unroll
            for (int kk2 = 0; kk2 < 2; kk2++) {
                const uint32_t koff = c * AT_CHUNK + kk2 * 32;
                uint32_t qa[4], kb[2][4];
                ldsm4(qa, sQ + koff + (wm * 16 + r_off) * 80 + c_off * 2);
#pragma unroll
                for (int u = 0; u < 2; u++)
                    ldsm4(kb[u], sK + koff + (wn * 32 + u * 16 + r_off) * 80 + c_off * 2);
#pragma unroll
                for (int u = 0; u < 2; u++) {
                    mma_bf16(sacc[u * 2],     qa, kb[u][0], kb[u][2]);
                    mma_bf16(sacc[u * 2 + 1], qa, kb[u][1], kb[u][3]);
                }
            }
        }
#pragma unroll
        for (int t = 0; t < 4; t++)
#pragma unroll
            for (int e = 0; e < 4; e++) sacc[t][e] *= 0.125f;

        float rm0 = -1e30f, rm1 = -1e30f;
#pragma unroll
        for (int t = 0; t < 4; t++) {
            rm0 = fmaxf(rm0, fmaxf(sacc[t][0], sacc[t][1]));
            rm1 = fmaxf(rm1, fmaxf(sacc[t][2], sacc[t][3]));
        }
        rm0 = fmaxf(rm0, __shfl_xor_sync(0xffffffffu, rm0, 1));
        rm0 = fmaxf(rm0, __shfl_xor_sync(0xffffffffu, rm0, 2));
        rm1 = fmaxf(rm1, __shfl_xor_sync(0xffffffffu, rm1, 1));
        rm1 = fmaxf(rm1, __shfl_xor_sync(0xffffffffu, rm1, 2));
        if ((lane & 3) == 0) {
            smax[wm][wn][g]     = rm0;
            smax[wm][wn][g + 8] = rm1;
        }
        __syncthreads();
        rm0 = fmaxf(rm0, smax[wm][wn ^ 1][g]);
        rm1 = fmaxf(rm1, smax[wm][wn ^ 1][g + 8]);

        const float mn0 = fmaxf(m0v, rm0);
        const float mn1 = fmaxf(m1v, rm1);
        const float a0 = __expf(m0v - mn0);
        const float a1 = __expf(m1v - mn1);
        m0v = mn0; m1v = mn1;

        float rs0 = 0.f, rs1 = 0.f;
#pragma unroll
        for (int t = 0; t < 4; t++) {
            sacc[t][0] = __expf(sacc[t][0] - mn0);
            sacc[t][1] = __expf(sacc[t][1] - mn0);
            sacc[t][2] = __expf(sacc[t][2] - mn1);
            sacc[t][3] = __expf(sacc[t][3] - mn1);
            rs0 += sacc[t][0] + sacc[t][1];
            rs1 += sacc[t][2] + sacc[t][3];
        }
        rs0 += __shfl_xor_sync(0xffffffffu, rs0, 1);
        rs0 += __shfl_xor_sync(0xffffffffu, rs0, 2);
        rs1 += __shfl_xor_sync(0xffffffffu, rs1, 1);
        rs1 += __shfl_xor_sync(0xffffffffu, rs1, 2);
        l0v = l0v * a0 + rs0;
        l1v = l1v * a1 + rs1;
#pragma unroll
        for (int t = 0; t < 8; t++) {
            ctx[t][0] *= a0; ctx[t][1] *= a0;
            ctx[t][2] *= a1; ctx[t][3] *= a1;
        }

        uint32_t pah[2][4];
#pragma unroll
        for (int kk2 = 0; kk2 < 2; kk2++) {
#pragma unroll
            for (int half = 0; half < 2; half++) {
                const int tt = 2 * kk2 + half;
                pah[kk2][half * 2 + 0] = pack_f2(sacc[tt][0], sacc[tt][1]);
                pah[kk2][half * 2 + 1] = pack_f2(sacc[tt][2], sacc[tt][3]);
            }
        }

#pragma unroll
        for (int kk2 = 0; kk2 < 2; kk2++) {
            const uint32_t voff = wn * AT_CHUNK + kk2 * 32;
#pragma unroll
            for (int u = 0; u < 4; u++) {
                uint32_t vb[4];
                ldsm4(vb, sV + voff + (u * 16 + r_off) * 80 + c_off * 2);
                mma_bf16(ctx[u * 2],     pah[kk2], vb[0], vb[2]);
                mma_bf16(ctx[u * 2 + 1], pah[kk2], vb[1], vb[3]);
            }
        }
    }

    __syncthreads();
    float* csum = (float*)(dsm + AT_TILE);
    if (wn == 1) {
#pragma unroll
        for (int t = 0; t < 8; t++) {
            const int u = t >> 1, v = t & 1;
            const int colb = u * 16 + v * 8 + t2;
            csum[(wm * 16 + g) * 68 + colb]         = ctx[t][0];
            csum[(wm * 16 + g) * 68 + colb + 1]     = ctx[t][1];
            csum[(wm * 16 + g + 8) * 68 + colb]     = ctx[t][2];
            csum[(wm * 16 + g + 8) * 68 + colb + 1] = ctx[t][3];
        }
    }
    if ((lane & 3) == 0) {
        larr[wn][wm * 16 + g]     = l0v;
        larr[wn][wm * 16 + g + 8] = l1v;
    }
    __syncthreads();
    if (wn == 0) {
#pragma unroll
        for (int t = 0; t < 8; t++) {
            const int u = t >> 1, v = t & 1;
            const int colb = u * 16 + v * 8 + t2;
            csum[(wm * 16 + g) * 68 + colb]         += ctx[t][0];
            csum[(wm * 16 + g) * 68 + colb + 1]     += ctx[t][1];
            csum[(wm * 16 + g + 8) * 68 + colb]     += ctx[t][2];
            csum[(wm * 16 + g + 8) * 68 + colb + 1] += ctx[t][3];
        }
    }
    __syncthreads();
#pragma unroll
    for (int i = 0; i < 4; i++) {
        const int idx = i * 256 + tid;
        const int row = idx >> 4, c4 = (idx & 15) * 4;
        const float inv = 1.f / (larr[0][row] + larr[1][row]);
        float4 v = *(float4*)&csum[row * 68 + c4];
        *(uint2*)(Oh + (qrow0 + row) * Hd + hoff + c4) =
            make_uint2(pack_f2(v.x * inv, v.y * inv),
                       pack_f2(v.z * inv, v.w * inv));
    }
}

// ---------------------------------------------------------------------------
// Merged conversion (all six fp32->bf16 tensors in one launch)
// ---------------------------------------------------------------------------
constexpr int CB_HS  = BS * Hd / 1024;
constexpr int CB_WQ  = (int)(NL * HH / 1024);
constexpr int CB_WK  = CB_WQ;
constexpr int CB_INW = (int)(3 * HH / 1024);
constexpr int CB_OW  = (int)(HH / 1024);
constexpr int CB_PW  = CB_OW;
constexpr int CB_TOT = CB_HS + CB_WQ + CB_WK + CB_INW + CB_OW + CB_PW;

__global__ __launch_bounds__(256) void k_conv_all(
    const float* __restrict__ hs,  bf16* __restrict__ hs_h,
    const float* __restrict__ wq,  bf16* __restrict__ wq_h,
    const float* __restrict__ wk,  bf16* __restrict__ wk_h,
    const float* __restrict__ inw, bf16* __restrict__ inw_h,
    const float* __restrict__ ow,  bf16* __restrict__ ow_h,
    const float* __restrict__ pw,  bf16* __restrict__ pw_h)
{
    long long bid = blockIdx.x;
    const float* src;
    bf16* dst;
    if (bid < CB_HS)                               { src = hs;  dst = hs_h; }
    else if ((bid -= CB_HS)  < CB_WQ)              { src = wq;  dst = wq_h; }
    else if ((bid -= CB_WQ)  < CB_WK)              { src = wk;  dst = wk_h; }
    else if ((bid -= CB_WK)  < CB_INW)             { src = inw; dst = inw_h; }
    else if ((bid -= CB_INW) < CB_OW)              { src = ow;  dst = ow_h; }
    else                     { bid -= CB_OW;         src = pw;  dst = pw_h; }
    const long long i4 = (bid * 256 + threadIdx.x) * 4;
    float4 v = *(const float4*)(src + i4);
    *(uint2*)(dst + i4) = make_uint2(pack_f2(v.x, v.y), pack_f2(v.z, v.w));
}

// ---------------------------------------------------------------------------
// Chain leaves (+flags folded in) / LN
// ---------------------------------------------------------------------------
__global__ __launch_bounds__(256) void k_factors(
    const float* __restrict__ alignT, const int* __restrict__ lang,
    bf16* __restrict__ Fh, bf16* __restrict__ FTh,
    unsigned char* fF, unsigned char* fP1, unsigned char* fP2)
{
    if (blockIdx.x == 0 && blockIdx.y == 0 && threadIdx.x == 0) {
        for (int a = 0; a < NL; a++) {
            for (int j = 0; j < 8; j++) fF[a * 8 + j] = (lang[j] == a) ? 1 : 0;
            for (int p = 0; p < 4; p++)
                fP1[a * 4 + p] = fF[a * 8 + 2 * p] & fF[a * 8 + 2 * p + 1];
            for (int p = 0; p < 2; p++)
                fP2[a * 2 + p] = fP1[a * 4 + 2 * p] & fP1[a * 4 + 2 * p + 1];
        }
    }

    const int node = blockIdx.y;
    const int a = node >> 3, j = node & 7;
    const int c = __ldg(&lang[j]);
    const long long nb = (long long)node * HH;
    const long long i4 = ((long long)blockIdx.x * 256 + threadIdx.x) * 4;
    const int r = (int)(i4 / Hd), col = (int)(i4 % Hd);

    if (c == a) {
        float v0 = (col + 0 == r) ? 1.f : 0.f;
        float v1 = (col + 1 == r) ? 1.f : 0.f;
        float v2 = (col + 2 == r) ? 1.f : 0.f;
        float v3 = (col + 3 == r) ? 1.f : 0.f;
        uint2 hv = make_uint2(pack_f2(v0, v1), pack_f2(v2, v3));
        *(uint2*)(Fh + nb + i4)  = hv;
        *(uint2*)(FTh + nb + i4) = hv;
    } else {
        const float* sm = alignT + (long long)(a * NL + c) * HH;
        float4 v = *(const float4*)(sm + i4);
        *(uint2*)(Fh + nb + i4) =
            make_uint2(pack_f2(v.x, v.y), pack_f2(v.z, v.w));
        float t0 = sm[(long long)(col + 0) * Hd + r];
        float t1 = sm[(long long)(col + 1) * Hd + r];
        float t2 = sm[(long long)(col + 2) * Hd + r];
        float t3 = sm[(long long)(col + 3) * Hd + r];
        *(uint2*)(FTh + nb + i4) =
            make_uint2(pack_f2(t0, t1), pack_f2(t2, t3));
    }
}

__global__ __launch_bounds__(256) void k_ln(
    const float* __restrict__ X, const float* __restrict__ Rres,
    const float* __restrict__ gam, const float* __restrict__ bet,
    float* __restrict__ out)
{
    const int row = blockIdx.x;
    const long long base = (long long)row * Hd;
    const int tid = threadIdx.x;

    float v[3];
    float s = 0.f, s2 = 0.f;
#pragma unroll
    for (int u = 0; u < 3; u++) {
        const int idx = tid + u * 256;
        const float val = X[base + idx] + Rres[base + idx];
        v[u] = val; s += val; s2 += val * val;
    }
#pragma unroll
    for (int off = 16; off >= 1; off >>= 1) {
        s  += __shfl_xor_sync(0xffffffffu, s, off);
        s2 += __shfl_xor_sync(0xffffffffu, s2, off);
    }
    __shared__ float ss[8], ss2[8], mv[2];
    const int wid = tid >> 5, lane = tid & 31;
    if (lane == 0) { ss[wid] = s; ss2[wid] = s2; }
    __syncthreads();
    if (tid == 0) {
        float S_ = 0.f, S2_ = 0.f;
        for (int w = 0; w < 8; w++) { S_ += ss[w]; S2_ += ss2[w]; }
        const float mean = S_ * (1.f / 768.f);
        const float var  = S2_ * (1.f / 768.f) - mean * mean;
        mv[0] = mean;
        mv[1] = rsqrtf(var + 1e-5f);
    }
    __syncthreads();
    const float mean = mv[0], rstd = mv[1];
#pragma unroll
    for (int u = 0; u < 3; u++) {
        const int idx = tid + u * 256;
        out[base + idx] = (v[u] - mean) * rstd * gam[idx] + bet[idx];
    }
}

// ---------------------------------------------------------------------------
// kernel_launch (9 launches)
// ---------------------------------------------------------------------------
#define SYM(v, s) cudaGetSymbolAddress((void**)&v, s)

extern "C" void kernel_launch(void* const* d_in, const int* in_sizes, int n_in,
                              void* d_out, int out_size)
{
    const float* hs      = (const float*)d_in[0];
    const int*   lang    = (const int*)  d_in[1];
    const float* Wq_lang = (const float*)d_in[3];
    const float* bq_lang = (const float*)d_in[4];
    const float* Wk_lang = (const float*)d_in[5];
    const float* bk_lang = (const float*)d_in[6];
    const float* in_w    = (const float*)d_in[7];
    const float* in_b    = (const float*)d_in[8];
    const float* out_w   = (const float*)d_in[9];
    const float* out_b   = (const float*)d_in[10];
    const float* alignT  = (const float*)d_in[11];
    const float* proj_w  = (const float*)d_in[12];
    const float* proj_b  = (const float*)d_in[13];
    const float* ln_g    = (const float*)d_in[14];
    const float* ln_b    = (const float*)d_in[15];
    float* out = (float*)d_out;

    float* obuf;
    SYM(obuf, g_o);

    bf16 *hs_h, *q_h, *k_h, *Qh, *Kh, *Vh, *ctx_h, *al_h;
    SYM(hs_h, g_hs_h); SYM(q_h, g_q_h); SYM(k_h, g_k_h);
    SYM(Qh, g_Qh); SYM(Kh, g_Kh); SYM(Vh, g_Vh);
    SYM(ctx_h, g_ctx_h); SYM(al_h, g_al_h);

    bf16 *Wq_h, *Wk_h, *inw_h, *ow_h, *pw_h;
    SYM(Wq_h, g_Wq_h); SYM(Wk_h, g_Wk_h);
    SYM(inw_h, g_inw_h); SYM(ow_h, g_ow_h); SYM(pw_h, g_pw_h);

    bf16 *F_h, *FT_h, *P1_h, *QT1_h, *P2_h, *QT2_h, *M_h, *MT_h, *GT_h;
    SYM(F_h, g_F_h);   SYM(FT_h, g_FT_h);
    SYM(P1_h, g_P1_h); SYM(QT1_h, g_QT1_h);
    SYM(P2_h, g_P2_h); SYM(QT2_h, g_QT2_h);
    SYM(M_h, g_M_h);   SYM(MT_h, g_MT_h);
    SYM(GT_h, g_GT_h);

    unsigned char *fF, *fP1, *fP2;
    SYM(fF, g_fF); SYM(fP1, g_fP1); SYM(fP2, g_fP2);

    cudaFuncSetAttribute(k_l1,    cudaFuncAttributeMaxDynamicSharedMemorySize, GEMM_SMEM_FULL);
    cudaFuncSetAttribute(k_l2,    cudaFuncAttributeMaxDynamicSharedMemorySize, GEMM_SMEM_FULL);
    cudaFuncSetAttribute(k_l3,    cudaFuncAttributeMaxDynamicSharedMemorySize, GEMM_SMEM_FULL);
    cudaFuncSetAttribute(k_GT,    cudaFuncAttributeMaxDynamicSharedMemorySize, GEMM_SMEM_FULL);
    cudaFuncSetAttribute(k_final, cudaFuncAttributeMaxDynamicSharedMemorySize, GEMM_SMEM_FULL);
    cudaFuncSetAttribute(k_attn_tc, cudaFuncAttributeMaxDynamicSharedMemorySize, ATT_SMEM);

    const dim3 thr(256);

    // 1: all conversions
    k_conv_all<<<CB_TOT, thr>>>(hs, hs_h, Wq_lang, Wq_h, Wk_lang, Wk_h,
                                in_w, inw_h, out_w, ow_h, proj_w, pw_h);

    // 2: chain leaves (+flags)
    k_factors<<<dim3((int)(HH / 1024), NL * 8), thr>>>(
        alignT, lang, F_h, FT_h, fF, fP1, fP2);

    // 3: L1 = q/k lang projections + chain level 1
    k_l1<<<dim3(12, 6, 36), thr, GEMM_SMEM_FULL>>>(
        hs_h, Wq_h, Wk_h, bq_lang, bk_lang, lang, q_h, k_h,
        F_h, FT_h, fF, P1_h, QT1_h);

    // 4: L2 = QKV + chain level 2
    k_l2<<<dim3(12, 6, 34), thr, GEMM_SMEM_FULL>>>(
        q_h, k_h, hs_h, inw_h, in_b, Qh, Kh, Vh,
        P1_h, QT1_h, fP1, P2_h, QT2_h);

    // 5: attention
    k_attn_tc<<<dim3(S / 64, NH, Bsz), thr, ATT_SMEM>>>(Qh, Kh, Vh, ctx_h);

    // 6: L3 = out_proj + chain level 3
    k_l3<<<dim3(12, 6, 13), thr, GEMM_SMEM_FULL>>>(
        ctx_h, ow_h, out_b, al_h, P2_h, QT2_h, fP2, M_h, MT_h);

    // 7: GT[l] = proj_w @ M[l]^T
    k_GT<<<dim3(12, 6, NL), thr, GEMM_SMEM_FULL>>>(pw_h, M_h, GT_h);

    // 8: fused final: out = al @ G[lang] + proj_b  (fp32)
    k_final<<<dim3(12, 6, Bsz), thr, GEMM_SMEM_FULL>>>(al_h, GT_h, proj_b, lang, obuf);

    // 9: residual + LayerNorm
    k_ln<<<BS, thr>>>(obuf, hs, ln_g, ln_b, out);
}

// round 16
// speedup vs baseline: 1.0076x; 1.0076x over previous
#include <cuda_runtime.h>
#include <cuda_bf16.h>
#include <cstdint>

// ---------------------------------------------------------------------------
// Problem constants
// ---------------------------------------------------------------------------
constexpr int Bsz = 8;
constexpr int S   = 768;
constexpr int Hd  = 768;
constexpr int NH  = 12;
constexpr int NL  = 5;
constexpr int BS  = Bsz * S;
constexpr long long HH = (long long)Hd * Hd;

typedef __nv_bfloat16 bf16;

// ---------------------------------------------------------------------------
// Scratch (hi-only)
// ---------------------------------------------------------------------------
__device__ float g_o  [BS * Hd];

__device__ bf16 g_hs_h [BS * Hd];
__device__ bf16 g_q_h  [BS * Hd];
__device__ bf16 g_k_h  [BS * Hd];
__device__ bf16 g_Qh   [BS * Hd];
__device__ bf16 g_Kh   [BS * Hd];
__device__ bf16 g_Vh   [BS * Hd];
__device__ bf16 g_ctx_h[BS * Hd];
__device__ bf16 g_al_h [BS * Hd];

__device__ bf16 g_Wq_h [NL * Hd * Hd];
__device__ bf16 g_Wk_h [NL * Hd * Hd];
__device__ bf16 g_inw_h[3 * Hd * Hd];
__device__ bf16 g_ow_h [Hd * Hd];
__device__ bf16 g_pw_h [Hd * Hd];

__device__ bf16 g_F_h [NL * 8 * Hd * Hd];
__device__ bf16 g_FT_h[NL * 8 * Hd * Hd];
__device__ bf16 g_P1_h[NL * 4 * Hd * Hd];
__device__ bf16 g_QT1_h[NL * 4 * Hd * Hd];
__device__ bf16 g_P2_h[NL * 2 * Hd * Hd];
__device__ bf16 g_QT2_h[NL * 2 * Hd * Hd];
__device__ bf16 g_M_h [NL * Hd * Hd];
__device__ bf16 g_MT_h[NL * Hd * Hd];
__device__ bf16 g_GT_h[NL * Hd * Hd];

__device__ unsigned char g_fF [NL * 8];
__device__ unsigned char g_fP1[NL * 4];
__device__ unsigned char g_fP2[NL * 2];

// ---------------------------------------------------------------------------
// PTX helpers
// ---------------------------------------------------------------------------
__device__ __forceinline__ uint32_t smem_u32(const void* p) {
    return (uint32_t)__cvta_generic_to_shared(p);
}
__device__ __forceinline__ void cp16(uint32_t d, const void* s) {
    asm volatile("cp.async.cg.shared.global [%0], [%1], 16;"
                 :: "r"(d), "l"(s) : "memory");
}
__device__ __forceinline__ void cp_commit() {
    asm volatile("cp.async.commit_group;" ::: "memory");
}
template <int N>
__device__ __forceinline__ void cp_wait() {
    asm volatile("cp.async.wait_group %0;" :: "n"(N) : "memory");
}
__device__ __forceinline__ void ldsm4(uint32_t* r, uint32_t addr) {
    asm volatile("ldmatrix.sync.aligned.m8n8.x4.shared.b16 {%0,%1,%2,%3}, [%4];"
                 : "=r"(r[0]), "=r"(r[1]), "=r"(r[2]), "=r"(r[3]) : "r"(addr));
}
__device__ __forceinline__ void mma_bf16(float* d, const uint32_t* a,
                                         uint32_t b0, uint32_t b1) {
    asm volatile(
        "mma.sync.aligned.m16n8k16.row.col.f32.bf16.bf16.f32 "
        "{%0,%1,%2,%3}, {%4,%5,%6,%7}, {%8,%9}, {%0,%1,%2,%3};"
        : "+f"(d[0]), "+f"(d[1]), "+f"(d[2]), "+f"(d[3])
        : "r"(a[0]), "r"(a[1]), "r"(a[2]), "r"(a[3]), "r"(b0), "r"(b1));
}
__device__ __forceinline__ uint32_t pack_bf(bf16 a, bf16 b) {
    return (uint32_t)__bfloat16_as_ushort(a) |
           ((uint32_t)__bfloat16_as_ushort(b) << 16);
}
__device__ __forceinline__ uint32_t pack_f2(float a, float b) {
    return pack_bf(__float2bfloat16(a), __float2bfloat16(b));
}

// ---------------------------------------------------------------------------
// GEMM: 128x128 tile, BLK_K=32, 8 warps, 4-stage pipeline (R14 best config).
// ---------------------------------------------------------------------------
constexpr int SKP     = 40;
constexpr int TILE_B  = 128 * SKP * 2;       // 10240 B
constexpr int STAGE_B = 2 * TILE_B;          // 20480 B (A, W)
constexpr int NSTAGE  = 4;
constexpr int GEMM_SMEM_FULL = NSTAGE * STAGE_B;   // 81920 B (> epilogue 67584)

__device__ __forceinline__ void gemm_issue(
    const bf16* __restrict__ base, int lw, uint32_t sdst0, int kc)
{
    const bf16* g0 = base + kc * 32;
#pragma unroll
    for (int i = 0; i < 4; i++) {
        const int chunk = i * 128 + lw;
        const int row = chunk >> 2, cs = chunk & 3;
        cp16(sdst0 + row * (SKP * 2) + cs * 16,
             g0 + (long long)row * Hd + cs * 8);
    }
}

// MODE 0: fp32 out (+bias). MODE 1: bf16 out (+bias if non-null).
// MODE 2: bf16 out + transposed bf16 out (no bias).
template <int MODE>
__device__ void gemm_core(
    const bf16* __restrict__ A, const bf16* __restrict__ W,
    const float* __restrict__ bias,
    float* __restrict__ C, bf16* __restrict__ Ch, bf16* __restrict__ Th,
    int m0, int n0)
{
    extern __shared__ char dsm[];
    const int tid = threadIdx.x;
    const int wid = tid >> 5, lane = tid & 31;
    const int m_off = (wid & 3) * 32;
    const int n_off = (wid >> 2) * 64;
    const uint32_t sbase = smem_u32(dsm);

    const int ltile = tid >> 7;          // 0 = A, 1 = W
    const int lw = tid & 127;
    const bf16* gbase = (ltile == 0) ? A + (long long)m0 * Hd
                                     : W + (long long)n0 * Hd;
    const uint32_t sdst_tile = ltile * TILE_B;

#pragma unroll
    for (int p = 0; p < NSTAGE - 1; p++) {
        gemm_issue(gbase, lw, sbase + p * STAGE_B + sdst_tile, p);
        cp_commit();
    }

    float acc[2][8][4];
#pragma unroll
    for (int mi = 0; mi < 2; mi++)
#pragma unroll
        for (int j = 0; j < 8; j++)
#pragma unroll
            for (int e = 0; e < 4; e++) acc[mi][j][e] = 0.f;

    const int r_off = ((lane >> 3) & 1) * 8 + (lane & 7);
    const int c_off = (lane >> 4) * 8;

    for (int kc = 0; kc < 24; kc++) {
        cp_wait<NSTAGE - 2>();
        __syncthreads();
        const uint32_t sb = sbase + (kc & (NSTAGE - 1)) * STAGE_B;
        const uint32_t aA = sb + (m_off + r_off) * (SKP * 2) + c_off * 2;
        const uint32_t aW = sb + TILE_B + (n_off + r_off) * (SKP * 2) + c_off * 2;

#pragma unroll
        for (int kk = 0; kk < 2; kk++) {
            uint32_t ah[2][4], bh[4][4];
#pragma unroll
            for (int t = 0; t < 2; t++)
                ldsm4(ah[t], aA + t * 16 * (SKP * 2) + kk * 32);
#pragma unroll
            for (int u = 0; u < 4; u++)
                ldsm4(bh[u], aW + u * 16 * (SKP * 2) + kk * 32);
#pragma unroll
            for (int u = 0; u < 4; u++)
#pragma unroll
                for (int mi = 0; mi < 2; mi++) {
                    mma_bf16(acc[mi][2 * u],     ah[mi], bh[u][0], bh[u][2]);
                    mma_bf16(acc[mi][2 * u + 1], ah[mi], bh[u][1], bh[u][3]);
                }
        }
        if (kc + NSTAGE - 1 < 24)
            gemm_issue(gbase, lw,
                       sbase + ((kc + NSTAGE - 1) & (NSTAGE - 1)) * STAGE_B + sdst_tile,
                       kc + NSTAGE - 1);
        cp_commit();
    }
    __syncthreads();

    float* sf = (float*)dsm;
    const int g = lane >> 2, t2 = (lane & 3) * 2;
#pragma unroll
    for (int mi = 0; mi < 2; mi++)
#pragma unroll
        for (int j = 0; j < 8; j++) {
            const int r = m_off + mi * 16 + g;
            const int c = n_off + j * 8 + t2;
            sf[r * 132 + c]           = acc[mi][j][0];
            sf[r * 132 + c + 1]       = acc[mi][j][1];
            sf[(r + 8) * 132 + c]     = acc[mi][j][2];
            sf[(r + 8) * 132 + c + 1] = acc[mi][j][3];
        }
    __syncthreads();

    if (MODE == 0) {
#pragma unroll 4
        for (int i = 0; i < 16; i++) {
            const int task = i * 256 + tid;
            const int row = task >> 5, c4 = (task & 31) * 4;
            float4 v = *(float4*)&sf[row * 132 + c4];
            v.x += bias[n0 + c4 + 0];
            v.y += bias[n0 + c4 + 1];
            v.z += bias[n0 + c4 + 2];
            v.w += bias[n0 + c4 + 3];
            *(float4*)(C + (long long)(m0 + row) * Hd + n0 + c4) = v;
        }
    } else {
#pragma unroll 4
        for (int i = 0; i < 16; i++) {
            const int task = i * 256 + tid;
            const int row = task >> 5, c4 = (task & 31) * 4;
            float4 v = *(float4*)&sf[row * 132 + c4];
            if (MODE == 1 && bias) {
                v.x += bias[n0 + c4 + 0];
                v.y += bias[n0 + c4 + 1];
                v.z += bias[n0 + c4 + 2];
                v.w += bias[n0 + c4 + 3];
            }
            *(uint2*)(Ch + (long long)(m0 + row) * Hd + n0 + c4) =
                make_uint2(pack_f2(v.x, v.y), pack_f2(v.z, v.w));
        }
        if (MODE == 2) {
            const int c = tid & 127;
            const int half = tid >> 7;
#pragma unroll 4
            for (int i = 0; i < 16; i++) {
                const int r4 = half * 64 + i * 4;
                float v0 = sf[(r4 + 0) * 132 + c];
                float v1 = sf[(r4 + 1) * 132 + c];
                float v2 = sf[(r4 + 2) * 132 + c];
                float v3 = sf[(r4 + 3) * 132 + c];
                *(uint2*)(Th + (long long)(n0 + c) * Hd + m0 + r4) =
                    make_uint2(pack_f2(v0, v1), pack_f2(v2, v3));
            }
        }
    }
}

// ---------------------------------------------------------------------------
// Chain product block
// ---------------------------------------------------------------------------
__device__ void chain_work(
    int zz,
    const bf16* __restrict__ sN_h, const bf16* __restrict__ sT_h,
    const unsigned char* __restrict__ fs,
    bf16* __restrict__ dN_h, bf16* __restrict__ dT_h,
    int spa, int dpa)
{
    const int a = zz / dpa, p = zz - a * dpa;
    const int li = a * spa + 2 * p;
    const unsigned char f1 = fs[li], f2 = fs[li + 1];
    const long long zo = (long long)zz * HH;
    const int m0 = blockIdx.y * 128, n0 = blockIdx.x * 128;
    const int tid = threadIdx.x;

    if (f1 & f2) {
#pragma unroll 4
        for (int i = 0; i < 16; i++) {
            const int task = i * 256 + tid;
            const int row = task >> 5, c4 = (task & 31) * 4;
            const int gr = m0 + row, gc = n0 + c4;
            float v0 = (gc + 0 == gr) ? 1.f : 0.f;
            float v1 = (gc + 1 == gr) ? 1.f : 0.f;
            float v2 = (gc + 2 == gr) ? 1.f : 0.f;
            float v3 = (gc + 3 == gr) ? 1.f : 0.f;
            const long long off = zo + (long long)gr * Hd + gc;
            uint2 hv = make_uint2(pack_f2(v0, v1), pack_f2(v2, v3));
            *(uint2*)(dN_h + off) = hv;
            *(uint2*)(dT_h + off) = hv;
        }
        return;
    }
    if (f1 | f2) {
        const long long so = (long long)(f1 ? li + 1 : li) * HH;
#pragma unroll 4
        for (int i = 0; i < 8; i++) {
            const int idx = i * 256 + tid;
            const int row = idx >> 4, c8 = (idx & 15) * 8;
            const long long doff = zo + (long long)(m0 + row) * Hd + n0 + c8;
            const long long soff = so + (long long)(m0 + row) * Hd + n0 + c8;
            *(uint4*)(dN_h + doff) = *(const uint4*)(sN_h + soff);
            *(uint4*)(dT_h + doff) = *(const uint4*)(sT_h + soff);
        }
        return;
    }
    gemm_core<2>(sN_h + (long long)li * HH, sT_h + (long long)(li + 1) * HH,
                 nullptr, nullptr, dN_h + zo, dT_h + zo, m0, n0);
}

// ---------------------------------------------------------------------------
// Merged launches
// ---------------------------------------------------------------------------
__global__ __launch_bounds__(256, 2) void k_l1(
    const bf16* __restrict__ hs_h,
    const bf16* __restrict__ Wq_h, const bf16* __restrict__ Wk_h,
    const float* __restrict__ bq, const float* __restrict__ bk,
    const int* __restrict__ lang,
    bf16* __restrict__ q_h, bf16* __restrict__ k_h,
    const bf16* __restrict__ F_h, const bf16* __restrict__ FT_h,
    const unsigned char* __restrict__ fF,
    bf16* __restrict__ P1_h, bf16* __restrict__ QT1_h)
{
    const int z = blockIdx.z;
    if (z < 16) {
        const int fam = z >> 3, b = z & 7;
        const int lg = __ldg(&lang[b]);
        const long long ao = (long long)b * S * Hd;
        const bf16* wh = (fam ? Wk_h : Wq_h) + (long long)lg * HH;
        const float* bs = (fam ? bk : bq) + lg * Hd;
        bf16* oh = (fam ? k_h : q_h) + ao;
        gemm_core<1>(hs_h + ao, wh, bs, nullptr, oh, nullptr,
                     blockIdx.y * 128, blockIdx.x * 128);
    } else {
        chain_work(z - 16, F_h, FT_h, fF, P1_h, QT1_h, 8, 4);
    }
}

__global__ __launch_bounds__(256, 2) void k_l2(
    const bf16* __restrict__ q_h, const bf16* __restrict__ k_h,
    const bf16* __restrict__ hs_h,
    const bf16* __restrict__ inw_h, const float* __restrict__ in_b,
    bf16* __restrict__ Qh, bf16* __restrict__ Kh, bf16* __restrict__ Vh,
    const bf16* __restrict__ P1_h, const bf16* __restrict__ QT1_h,
    const unsigned char* __restrict__ fP1,
    bf16* __restrict__ P2_h, bf16* __restrict__ QT2_h)
{
    const int z = blockIdx.z;
    if (z < 24) {
        const int kind = z >> 3, b = z & 7;
        const long long ao = (long long)b * S * Hd;
        const bf16* ah;
        bf16* oh;
        if (kind == 0)      { ah = q_h;  oh = Qh; }
        else if (kind == 1) { ah = k_h;  oh = Kh; }
        else                { ah = hs_h; oh = Vh; }
        gemm_core<1>(ah + ao, inw_h + (long long)kind * HH, in_b + kind * Hd,
                     nullptr, oh + ao, nullptr,
                     blockIdx.y * 128, blockIdx.x * 128);
    } else {
        chain_work(z - 24, P1_h, QT1_h, fP1, P2_h, QT2_h, 4, 2);
    }
}

__global__ __launch_bounds__(256, 2) void k_l3(
    const bf16* __restrict__ ctx_h,
    const bf16* __restrict__ ow_h, const float* __restrict__ out_b,
    bf16* __restrict__ al_h,
    const bf16* __restrict__ P2_h, const bf16* __restrict__ QT2_h,
    const unsigned char* __restrict__ fP2,
    bf16* __restrict__ M_h, bf16* __restrict__ MT_h)
{
    const int z = blockIdx.z;
    if (z < 8) {
        const long long ao = (long long)z * S * Hd;
        gemm_core<1>(ctx_h + ao, ow_h, out_b, nullptr, al_h + ao, nullptr,
                     blockIdx.y * 128, blockIdx.x * 128);
    } else {
        chain_work(z - 8, P2_h, QT2_h, fP2, M_h, MT_h, 2, 1);
    }
}

// GT[l] = proj_w @ M[l]^T
__global__ __launch_bounds__(256, 2) void k_GT(
    const bf16* __restrict__ pw_h, const bf16* __restrict__ M_h,
    bf16* __restrict__ GT_h)
{
    const long long lo = (long long)blockIdx.z * HH;
    gemm_core<1>(pw_h, M_h + lo, nullptr, nullptr, GT_h + lo, nullptr,
                 blockIdx.y * 128, blockIdx.x * 128);
}

// final: out[b] = al[b] @ G[lang[b]] + proj_b
__global__ __launch_bounds__(256, 2) void k_final(
    const bf16* __restrict__ al_h, const bf16* __restrict__ GT_h,
    const float* __restrict__ proj_b, const int* __restrict__ lang,
    float* __restrict__ C)
{
    const int z = blockIdx.z;
    const int lg = __ldg(&lang[z]);
    const long long ao = (long long)z * S * Hd;
    gemm_core<0>(al_h + ao, GT_h + (long long)lg * HH, proj_b,
                 C + ao, nullptr, nullptr,
                 blockIdx.y * 128, blockIdx.x * 128);
}

// ---------------------------------------------------------------------------
// Tensor-core flash attention, hi-only, PIPELINED K/V loads.
// smem: Q | K0 | K1 | Vr0 | Vr1 | VT    (csum aliases Vr0 region)
// ---------------------------------------------------------------------------
constexpr int AT_CHUNK = 64 * 80;
constexpr int AT_TILE  = 2 * AT_CHUNK;       // 10240 B
constexpr int ATT_SMEM = 6 * AT_TILE;        // 61440 B

__global__ __launch_bounds__(256) void k_attn_tc(
    const bf16* __restrict__ Qg, const bf16* __restrict__ Kg,
    const bf16* __restrict__ Vg, bf16* __restrict__ Oh)
{
    extern __shared__ char dsm[];
    __shared__ float smax[4][2][16];
    __shared__ float larr[2][64];

    const int qt = blockIdx.x, h = blockIdx.y, b = blockIdx.z;
    const int tid = threadIdx.x;
    const int wid = tid >> 5, lane = tid & 31;
    const int wm = wid & 3, wn = wid >> 2;
    const int g = lane >> 2, t2 = (lane & 3) * 2;
    const int r_off = ((lane >> 3) & 1) * 8 + (lane & 7);
    const int c_off = (lane >> 4) * 8;

    const uint32_t sQ  = smem_u32(dsm);
    const uint32_t sK0 = sQ + AT_TILE;          // K buffers at +1,+2 tiles
    const uint32_t sVr0= sQ + 3 * AT_TILE;      // raw V buffers at +3,+4
    const uint32_t sVT = sQ + 5 * AT_TILE;      // transposed V
    unsigned short* vt16 = (unsigned short*)(dsm + 5 * AT_TILE);

    const long long qrow0 = (long long)(b * S + qt * 64);
    const int hoff = h * 64;

    // Q load + K/V prologue (groups 0,1)
#pragma unroll
    for (int i = 0; i < 2; i++) {
        const int task = i * 256 + tid;
        const int row = task >> 3, rem = task & 7;
        const int chunk = rem >> 2, sub = rem & 3;
        cp16(sQ + chunk * AT_CHUNK + row * 80 + sub * 16,
             Qg + (qrow0 + row) * Hd + hoff + chunk * 32 + sub * 8);
    }
#pragma unroll
    for (int p = 0; p < 2; p++) {
        const long long krow0 = (long long)(b * S + p * 64);
#pragma unroll
        for (int i = 0; i < 2; i++) {
            const int task = i * 256 + tid;
            const int row = task >> 3, rem = task & 7;
            const int chunk = rem >> 2, sub = rem & 3;
            const uint32_t off = chunk * AT_CHUNK + row * 80 + sub * 16;
            const long long gs = (krow0 + row) * Hd + hoff + chunk * 32 + sub * 8;
            cp16(sK0  + p * AT_TILE + off, Kg + gs);
            cp16(sVr0 + p * AT_TILE + off, Vg + gs);
        }
        cp_commit();
    }

    float m0v = -1e30f, m1v = -1e30f, l0v = 0.f, l1v = 0.f;
    float ctx[8][4];
#pragma unroll
    for (int t = 0; t < 8; t++)
#pragma unroll
        for (int e = 0; e < 4; e++) ctx[t][e] = 0.f;

    for (int kt = 0; kt < 12; kt++) {
        cp_wait<1>();                 // group kt complete (Q rides group 0)
        __syncthreads();              // all warps done with VT / smax / old buffers
        const int buf = kt & 1;
        const uint32_t sK = sK0 + buf * AT_TILE;

        // transpose raw V (smem -> smem)
        {
            const char* vr = dsm + 3 * AT_TILE + buf * AT_TILE;
#pragma unroll
            for (int i = 0; i < 8; i++) {
                const int task = i * 256 + tid;
                const int r = task >> 5;
                const int c2 = (task & 31) * 2;
                const uint32_t v2 = *(const uint32_t*)(
                    vr + (c2 >> 5) * AT_CHUNK + r * 80 + (c2 & 31) * 2);
                const int base = (r >> 5) * 2560 + (r & 31);
                vt16[base + c2 * 40]       = (unsigned short)(v2 & 0xffff);
                vt16[base + (c2 + 1) * 40] = (unsigned short)(v2 >> 16);
            }
        }

        // QK^T
        float sacc[4][4];
#pragma unroll
        for (int t = 0; t < 4; t++)
#pragma unroll
            for (int e = 0; e < 4; e++) sacc[t][e] = 0.f;

#pragma unroll
        for (int c = 0; c < 2; c++) {
#pragma unroll
            for (int kk2 = 0; kk2 < 2; kk2++) {
                const uint32_t koff = c * AT_CHUNK + kk2 * 32;
                uint32_t qa[4], kb[2][4];
                ldsm4(qa, sQ + koff + (wm * 16 + r_off) * 80 + c_off * 2);
#pragma unroll
                for (int u = 0; u < 2; u++)
                    ldsm4(kb[u], sK + koff + (wn * 32 + u * 16 + r_off) * 80 + c_off * 2);
#pragma unroll
                for (int u = 0; u < 2; u++) {
                    mma_bf16(sacc[u * 2],     qa, kb[u][0], kb[u][2]);
                    mma_bf16(sacc[u * 2 + 1], qa, kb[u][1], kb[u][3]);
                }
            }
        }
#pragma unroll
        for (int t = 0; t < 4; t++)
#pragma unroll
            for (int e = 0; e < 4; e++) sacc[t][e] *= 0.125f;

        // row max
        float rm0 = -1e30f, rm1 = -1e30f;
#pragma unroll
        for (int t = 0; t < 4; t++) {
            rm0 = fmaxf(rm0, fmaxf(sacc[t][0], sacc[t][1]));
            rm1 = fmaxf(rm1, fmaxf(sacc[t][2], sacc[t][3]));
        }
        rm0 = fmaxf(rm0, __shfl_xor_sync(0xffffffffu, rm0, 1));
        rm0 = fmaxf(rm0, __shfl_xor_sync(0xffffffffu, rm0, 2));
        rm1 = fmaxf(rm1, __shfl_xor_sync(0xffffffffu, rm1, 1));
        rm1 = fmaxf(rm1, __shfl_xor_sync(0xffffffffu, rm1, 2));
        if ((lane & 3) == 0) {
            smax[wm][wn][g]     = rm0;
            smax[wm][wn][g + 8] = rm1;
        }
        __syncthreads();              // all warps done reading K[buf] + Vr[buf]
        rm0 = fmaxf(rm0, smax[wm][wn ^ 1][g]);
        rm1 = fmaxf(rm1, smax[wm][wn ^ 1][g + 8]);

        // issue K/V for kt+2 into buf (now free); uniform commit
        if (kt + 2 < 12) {
            const long long krow2 = (long long)(b * S + (kt + 2) * 64);
#pragma unroll
            for (int i = 0; i < 2; i++) {
                const int task = i * 256 + tid;
                const int row = task >> 3, rem = task & 7;
                const int chunk = rem >> 2, sub = rem & 3;
                const uint32_t off = chunk * AT_CHUNK + row * 80 + sub * 16;
                const long long gs = (krow2 + row) * Hd + hoff + chunk * 32 + sub * 8;
                cp16(sK0  + buf * AT_TILE + off, Kg + gs);
                cp16(sVr0 + buf * AT_TILE + off, Vg + gs);
            }
        }
        cp_commit();

        const float mn0 = fmaxf(m0v, rm0);
        const float mn1 = fmaxf(m1v, rm1);
        const float a0 = __expf(m0v - mn0);
        const float a1 = __expf(m1v - mn1);
        m0v = mn0; m1v = mn1;

        float rs0 = 0.f, rs1 = 0.f;
#pragma unroll
        for (int t = 0; t < 4; t++) {
            sacc[t][0] = __expf(sacc[t][0] - mn0);
            sacc[t][1] = __expf(sacc[t][1] - mn0);
            sacc[t][2] = __expf(sacc[t][2] - mn1);
            sacc[t][3] = __expf(sacc[t][3] - mn1);
            rs0 += sacc[t][0] + sacc[t][1];
            rs1 += sacc[t][2] + sacc[t][3];
        }
        rs0 += __shfl_xor_sync(0xffffffffu, rs0, 1);
        rs0 += __shfl_xor_sync(0xffffffffu, rs0, 2);
        rs1 += __shfl_xor_sync(0xffffffffu, rs1, 1);
        rs1 += __shfl_xor_sync(0xffffffffu, rs1, 2);
        l0v = l0v * a0 + rs0;
        l1v = l1v * a1 + rs1;
#pragma unroll
        for (int t = 0; t < 8; t++) {
            ctx[t][0] *= a0; ctx[t][1] *= a0;
            ctx[t][2] *= a1; ctx[t][3] *= a1;
        }

        uint32_t pah[2][4];
#pragma unroll
        for (int kk2 = 0; kk2 < 2; kk2++) {
#pragma unroll
            for (int half = 0; half < 2; half++) {
                const int tt = 2 * kk2 + half;
                pah[kk2][half * 2 + 0] = pack_f2(sacc[tt][0], sacc[tt][1]);
                pah[kk2][half * 2 + 1] = pack_f2(sacc[tt][2], sacc[tt][3]);
            }
        }

        // PV on transposed V (written this iter; visible via mid-iter sync)
#pragma unroll
        for (int kk2 = 0; kk2 < 2; kk2++) {
            const uint32_t voff = wn * AT_CHUNK + kk2 * 32;
#pragma unroll
            for (int u = 0; u < 4; u++) {
                uint32_t vb[4];
                ldsm4(vb, sVT + voff + (u * 16 + r_off) * 80 + c_off * 2);
                mma_bf16(ctx[u * 2],     pah[kk2], vb[0], vb[2]);
                mma_bf16(ctx[u * 2 + 1], pah[kk2], vb[1], vb[3]);
            }
        }
    }

    // merge kv-half partials; csum aliases Vr0 region
    __syncthreads();
    float* csum = (float*)(dsm + 3 * AT_TILE);
    if (wn == 1) {
#pragma unroll
        for (int t = 0; t < 8; t++) {
            const int u = t >> 1, v = t & 1;
            const int colb = u * 16 + v * 8 + t2;
            csum[(wm * 16 + g) * 68 + colb]         = ctx[t][0];
            csum[(wm * 16 + g) * 68 + colb + 1]     = ctx[t][1];
            csum[(wm * 16 + g + 8) * 68 + colb]     = ctx[t][2];
            csum[(wm * 16 + g + 8) * 68 + colb + 1] = ctx[t][3];
        }
    }
    if ((lane & 3) == 0) {
        larr[wn][wm * 16 + g]     = l0v;
        larr[wn][wm * 16 + g + 8] = l1v;
    }
    __syncthreads();
    if (wn == 0) {
#pragma unroll
        for (int t = 0; t < 8; t++) {
            const int u = t >> 1, v = t & 1;
            const int colb = u * 16 + v * 8 + t2;
            csum[(wm * 16 + g) * 68 + colb]         += ctx[t][0];
            csum[(wm * 16 + g) * 68 + colb + 1]     += ctx[t][1];
            csum[(wm * 16 + g + 8) * 68 + colb]     += ctx[t][2];
            csum[(wm * 16 + g + 8) * 68 + colb + 1] += ctx[t][3];
        }
    }
    __syncthreads();
#pragma unroll
    for (int i = 0; i < 4; i++) {
        const int idx = i * 256 + tid;
        const int row = idx >> 4, c4 = (idx & 15) * 4;
        const float inv = 1.f / (larr[0][row] + larr[1][row]);
        float4 v = *(float4*)&csum[row * 68 + c4];
        *(uint2*)(Oh + (qrow0 + row) * Hd + hoff + c4) =
            make_uint2(pack_f2(v.x * inv, v.y * inv),
                       pack_f2(v.z * inv, v.w * inv));
    }
}

// ---------------------------------------------------------------------------
// Merged conversion (all six fp32->bf16 tensors in one launch)
// ---------------------------------------------------------------------------
constexpr int CB_HS  = BS * Hd / 1024;
constexpr int CB_WQ  = (int)(NL * HH / 1024);
constexpr int CB_WK  = CB_WQ;
constexpr int CB_INW = (int)(3 * HH / 1024);
constexpr int CB_OW  = (int)(HH / 1024);
constexpr int CB_PW  = CB_OW;
constexpr int CB_TOT = CB_HS + CB_WQ + CB_WK + CB_INW + CB_OW + CB_PW;

__global__ __launch_bounds__(256) void k_conv_all(
    const float* __restrict__ hs,  bf16* __restrict__ hs_h,
    const float* __restrict__ wq,  bf16* __restrict__ wq_h,
    const float* __restrict__ wk,  bf16* __restrict__ wk_h,
    const float* __restrict__ inw, bf16* __restrict__ inw_h,
    const float* __restrict__ ow,  bf16* __restrict__ ow_h,
    const float* __restrict__ pw,  bf16* __restrict__ pw_h)
{
    long long bid = blockIdx.x;
    const float* src;
    bf16* dst;
    if (bid < CB_HS)                               { src = hs;  dst = hs_h; }
    else if ((bid -= CB_HS)  < CB_WQ)              { src = wq;  dst = wq_h; }
    else if ((bid -= CB_WQ)  < CB_WK)              { src = wk;  dst = wk_h; }
    else if ((bid -= CB_WK)  < CB_INW)             { src = inw; dst = inw_h; }
    else if ((bid -= CB_INW) < CB_OW)              { src = ow;  dst = ow_h; }
    else                     { bid -= CB_OW;         src = pw;  dst = pw_h; }
    const long long i4 = (bid * 256 + threadIdx.x) * 4;
    float4 v = *(const float4*)(src + i4);
    *(uint2*)(dst + i4) = make_uint2(pack_f2(v.x, v.y), pack_f2(v.z, v.w));
}

// ---------------------------------------------------------------------------
// Chain leaves (+flags folded in) / LN
// ---------------------------------------------------------------------------
__global__ __launch_bounds__(256) void k_factors(
    const float* __restrict__ alignT, const int* __restrict__ lang,
    bf16* __restrict__ Fh, bf16* __restrict__ FTh,
    unsigned char* fF, unsigned char* fP1, unsigned char* fP2)
{
    if (blockIdx.x == 0 && blockIdx.y == 0 && threadIdx.x == 0) {
        for (int a = 0; a < NL; a++) {
            for (int j = 0; j < 8; j++) fF[a * 8 + j] = (lang[j] == a) ? 1 : 0;
            for (int p = 0; p < 4; p++)
                fP1[a * 4 + p] = fF[a * 8 + 2 * p] & fF[a * 8 + 2 * p + 1];
            for (int p = 0; p < 2; p++)
                fP2[a * 2 + p] = fP1[a * 4 + 2 * p] & fP1[a * 4 + 2 * p + 1];
        }
    }

    const int node = blockIdx.y;
    const int a = node >> 3, j = node & 7;
    const int c = __ldg(&lang[j]);
    const long long nb = (long long)node * HH;
    const long long i4 = ((long long)blockIdx.x * 256 + threadIdx.x) * 4;
    const int r = (int)(i4 / Hd), col = (int)(i4 % Hd);

    if (c == a) {
        float v0 = (col + 0 == r) ? 1.f : 0.f;
        float v1 = (col + 1 == r) ? 1.f : 0.f;
        float v2 = (col + 2 == r) ? 1.f : 0.f;
        float v3 = (col + 3 == r) ? 1.f : 0.f;
        uint2 hv = make_uint2(pack_f2(v0, v1), pack_f2(v2, v3));
        *(uint2*)(Fh + nb + i4)  = hv;
        *(uint2*)(FTh + nb + i4) = hv;
    } else {
        const float* sm = alignT + (long long)(a * NL + c) * HH;
        float4 v = *(const float4*)(sm + i4);
        *(uint2*)(Fh + nb + i4) =
            make_uint2(pack_f2(v.x, v.y), pack_f2(v.z, v.w));
        float t0 = sm[(long long)(col + 0) * Hd + r];
        float t1 = sm[(long long)(col + 1) * Hd + r];
        float t2 = sm[(long long)(col + 2) * Hd + r];
        float t3 = sm[(long long)(col + 3) * Hd + r];
        *(uint2*)(FTh + nb + i4) =
            make_uint2(pack_f2(t0, t1), pack_f2(t2, t3));
    }
}

__global__ __launch_bounds__(256) void k_ln(
    const float* __restrict__ X, const float* __restrict__ Rres,
    const float* __restrict__ gam, const float* __restrict__ bet,
    float* __restrict__ out)
{
    const int row = blockIdx.x;
    const long long base = (long long)row * Hd;
    const int tid = threadIdx.x;

    float v[3];
    float s = 0.f, s2 = 0.f;
#pragma unroll
    for (int u = 0; u < 3; u++) {
        const int idx = tid + u * 256;
        const float val = X[base + idx] + Rres[base + idx];
        v[u] = val; s += val; s2 += val * val;
    }
#pragma unroll
    for (int off = 16; off >= 1; off >>= 1) {
        s  += __shfl_xor_sync(0xffffffffu, s, off);
        s2 += __shfl_xor_sync(0xffffffffu, s2, off);
    }
    __shared__ float ss[8], ss2[8], mv[2];
    const int wid = tid >> 5, lane = tid & 31;
    if (lane == 0) { ss[wid] = s; ss2[wid] = s2; }
    __syncthreads();
    if (tid == 0) {
        float S_ = 0.f, S2_ = 0.f;
        for (int w = 0; w < 8; w++) { S_ += ss[w]; S2_ += ss2[w]; }
        const float mean = S_ * (1.f / 768.f);
        const float var  = S2_ * (1.f / 768.f) - mean * mean;
        mv[0] = mean;
        mv[1] = rsqrtf(var + 1e-5f);
    }
    __syncthreads();
    const float mean = mv[0], rstd = mv[1];
#pragma unroll
    for (int u = 0; u < 3; u++) {
        const int idx = tid + u * 256;
        out[base + idx] = (v[u] - mean) * rstd * gam[idx] + bet[idx];
    }
}

// ---------------------------------------------------------------------------
// kernel_launch (9 launches)
// ---------------------------------------------------------------------------
#define SYM(v, s) cudaGetSymbolAddress((void**)&v, s)

extern "C" void kernel_launch(void* const* d_in, const int* in_sizes, int n_in,
                              void* d_out, int out_size)
{
    const float* hs      = (const float*)d_in[0];
    const int*   lang    = (const int*)  d_in[1];
    const float* Wq_lang = (const float*)d_in[3];
    const float* bq_lang = (const float*)d_in[4];
    const float* Wk_lang = (const float*)d_in[5];
    const float* bk_lang = (const float*)d_in[6];
    const float* in_w    = (const float*)d_in[7];
    const float* in_b    = (const float*)d_in[8];
    const float* out_w   = (const float*)d_in[9];
    const float* out_b   = (const float*)d_in[10];
    const float* alignT  = (const float*)d_in[11];
    const float* proj_w  = (const float*)d_in[12];
    const float* proj_b  = (const float*)d_in[13];
    const float* ln_g    = (const float*)d_in[14];
    const float* ln_b    = (const float*)d_in[15];
    float* out = (float*)d_out;

    float* obuf;
    SYM(obuf, g_o);

    bf16 *hs_h, *q_h, *k_h, *Qh, *Kh, *Vh, *ctx_h, *al_h;
    SYM(hs_h, g_hs_h); SYM(q_h, g_q_h); SYM(k_h, g_k_h);
    SYM(Qh, g_Qh); SYM(Kh, g_Kh); SYM(Vh, g_Vh);
    SYM(ctx_h, g_ctx_h); SYM(al_h, g_al_h);

    bf16 *Wq_h, *Wk_h, *inw_h, *ow_h, *pw_h;
    SYM(Wq_h, g_Wq_h); SYM(Wk_h, g_Wk_h);
    SYM(inw_h, g_inw_h); SYM(ow_h, g_ow_h); SYM(pw_h, g_pw_h);

    bf16 *F_h, *FT_h, *P1_h, *QT1_h, *P2_h, *QT2_h, *M_h, *MT_h, *GT_h;
    SYM(F_h, g_F_h);   SYM(FT_h, g_FT_h);
    SYM(P1_h, g_P1_h); SYM(QT1_h, g_QT1_h);
    SYM(P2_h, g_P2_h); SYM(QT2_h, g_QT2_h);
    SYM(M_h, g_M_h);   SYM(MT_h, g_MT_h);
    SYM(GT_h, g_GT_h);

    unsigned char *fF, *fP1, *fP2;
    SYM(fF, g_fF); SYM(fP1, g_fP1); SYM(fP2, g_fP2);

    cudaFuncSetAttribute(k_l1,    cudaFuncAttributeMaxDynamicSharedMemorySize, GEMM_SMEM_FULL);
    cudaFuncSetAttribute(k_l2,    cudaFuncAttributeMaxDynamicSharedMemorySize, GEMM_SMEM_FULL);
    cudaFuncSetAttribute(k_l3,    cudaFuncAttributeMaxDynamicSharedMemorySize, GEMM_SMEM_FULL);
    cudaFuncSetAttribute(k_GT,    cudaFuncAttributeMaxDynamicSharedMemorySize, GEMM_SMEM_FULL);
    cudaFuncSetAttribute(k_final, cudaFuncAttributeMaxDynamicSharedMemorySize, GEMM_SMEM_FULL);
    cudaFuncSetAttribute(k_attn_tc, cudaFuncAttributeMaxDynamicSharedMemorySize, ATT_SMEM);

    const dim3 thr(256);

    // 1: all conversions
    k_conv_all<<<CB_TOT, thr>>>(hs, hs_h, Wq_lang, Wq_h, Wk_lang, Wk_h,
                                in_w, inw_h, out_w, ow_h, proj_w, pw_h);

    // 2: chain leaves (+flags)
    k_factors<<<dim3((int)(HH / 1024), NL * 8), thr>>>(
        alignT, lang, F_h, FT_h, fF, fP1, fP2);

    // 3: L1 = q/k lang projections + chain level 1
    k_l1<<<dim3(6, 6, 36), thr, GEMM_SMEM_FULL>>>(
        hs_h, Wq_h, Wk_h, bq_lang, bk_lang, lang, q_h, k_h,
        F_h, FT_h, fF, P1_h, QT1_h);

    // 4: L2 = QKV + chain level 2
    k_l2<<<dim3(6, 6, 34), thr, GEMM_SMEM_FULL>>>(
        q_h, k_h, hs_h, inw_h, in_b, Qh, Kh, Vh,
        P1_h, QT1_h, fP1, P2_h, QT2_h);

    // 5: attention (pipelined K/V)
    k_attn_tc<<<dim3(S / 64, NH, Bsz), thr, ATT_SMEM>>>(Qh, Kh, Vh, ctx_h);

    // 6: L3 = out_proj + chain level 3
    k_l3<<<dim3(6, 6, 13), thr, GEMM_SMEM_FULL>>>(
        ctx_h, ow_h, out_b, al_h, P2_h, QT2_h, fP2, M_h, MT_h);

    // 7: GT[l] = proj_w @ M[l]^T
    k_GT<<<dim3(6, 6, NL), thr, GEMM_SMEM_FULL>>>(pw_h, M_h, GT_h);

    // 8: fused final: out = al @ G[lang] + proj_b  (fp32)
    k_final<<<dim3(6, 6, Bsz), thr, GEMM_SMEM_FULL>>>(al_h, GT_h, proj_b, lang, obuf);

    // 9: residual + LayerNorm
    k_ln<<<BS, thr>>>(obuf, hs, ln_g, ln_b, out);
}